// round 7
// baseline (speedup 1.0000x reference)
#include <cuda_runtime.h>
#include <stdint.h>
#include <math.h>

#define N_NODES 10000
#define N_EDGES 320000
#define IN_DIM  512
#define CH      128

// ---------------- scratch (device globals; zero-initialized at load) ----------------
__device__ float g_h  [N_NODES * CH];
__device__ float g_xw [N_NODES * CH];
__device__ float g_z1 [N_NODES * CH];
__device__ float g_dinv[N_NODES];
__device__ int   g_cnt [N_NODES];       // re-zeroed by decoder each run
__device__ int   g_pos [N_NODES];       // re-zeroed by decoder each run
__device__ int   g_off [N_NODES + 1];
__device__ int   g_src [N_EDGES];
__device__ int   g_tgt [N_EDGES];
__device__ int   g_adj [N_EDGES];
__device__ int   g_eid [N_EDGES];
__device__ float g_z2c0[N_NODES];

// z2: 8 rows per block, 1250 blocks total, split across the three fat kernels
#define Z2A_BLK 475    // rows [0, 3800)
#define Z2B_BLK 425    // rows [3800, 7200)
#define Z2C_BLK 350    // rows [7200, 10000)

#define GEMM_BLOCKS 157
#define AUX_BLOCKS  64          // cvt_count role (fatA) / fill role (fatB)

// ---------------- edge conversion (role inside fatA) ----------------
__device__ __forceinline__ bool edges_are_i64(const int* p) {
    bool b = true;
#pragma unroll
    for (int i = 0; i < 8; i++) b = b && (p[2 * i + 1] == 0);
    return b;
}

__device__ __forceinline__ void cvt_count_body(const int* __restrict__ ep, int bb) {
    bool i64 = edges_are_i64(ep);
    for (int e = threadIdx.x + bb * 256; e < N_EDGES; e += AUX_BLOCKS * 256) {
        int s, t;
        if (i64) {
            const long long* p = (const long long*)ep;
            s = (int)p[e]; t = (int)p[N_EDGES + e];
        } else {
            s = ep[e]; t = ep[N_EDGES + e];
        }
        g_src[e] = s; g_tgt[e] = t;
        atomicAdd(&g_cnt[t], 1);
    }
}

// ---------------- scan: exclusive prefix of cnt -> off, dinv = rsqrt(cnt+1) ----------------
__global__ void scan_kernel() {
    __shared__ int wsum[32];
    int tid = threadIdx.x, lane = tid & 31, wid = tid >> 5;
    int carry = 0;
    for (int base = 0; base < N_NODES; base += 1024) {
        int idx = base + tid;
        int v = (idx < N_NODES) ? g_cnt[idx] : 0;
        int x = v;
#pragma unroll
        for (int d = 1; d < 32; d <<= 1) {
            int y = __shfl_up_sync(0xffffffffu, x, d);
            if (lane >= d) x += y;
        }
        if (lane == 31) wsum[wid] = x;
        __syncthreads();
        if (wid == 0) {
            int s = wsum[lane];
#pragma unroll
            for (int d = 1; d < 32; d <<= 1) {
                int y = __shfl_up_sync(0xffffffffu, s, d);
                if (lane >= d) s += y;
            }
            wsum[lane] = s;
        }
        __syncthreads();
        int offset = wid ? wsum[wid - 1] : 0;
        if (idx < N_NODES) {
            g_off[idx] = carry + offset + x - v;
            g_dinv[idx] = rsqrtf((float)(v + 1));
        }
        carry += wsum[31];
        __syncthreads();
    }
    if (tid == 0) g_off[N_NODES] = carry;
}

// ---------------- tf32 MMA helpers ----------------
__device__ __forceinline__ unsigned f2tf32(float f) {
    unsigned u;
    asm("cvt.rna.tf32.f32 %0, %1;" : "=r"(u) : "f"(f));
    return u;
}

__device__ __forceinline__ void mma_tf32(float c[4], unsigned a0, unsigned a1,
                                         unsigned a2, unsigned a3,
                                         unsigned b0, unsigned b1) {
    asm volatile(
        "mma.sync.aligned.m16n8k8.row.col.f32.tf32.tf32.f32 "
        "{%0,%1,%2,%3}, {%4,%5,%6,%7}, {%8,%9}, {%0,%1,%2,%3};\n"
        : "+f"(c[0]), "+f"(c[1]), "+f"(c[2]), "+f"(c[3])
        : "r"(a0), "r"(a1), "r"(a2), "r"(a3), "r"(b0), "r"(b1));
}

#define WS_STRIDE 68
// smem: GEMM needs 128*68+64 = 8768 floats; z2 needs 8192 (2x8x128 float4) + 64
#define SMEM_FLOATS (128 * WS_STRIDE + 64)

// ---------------- tf32 GEMM block body: out[M,128] = A[M,K] @ W[128,K]^T ----------------
template <int KDIM, bool NORM, bool ROWSCALE>
__device__ __forceinline__ void gemm_tf32_body(
    const float* __restrict__ A, const float* __restrict__ W,
    const float* __restrict__ bias, const float* __restrict__ rs,
    float* __restrict__ out, int M, float scale, int m0, float* smem) {

    const int tid = threadIdx.x, lane = tid & 31, w = tid >> 5;
    const int gid = lane >> 2, tig = lane & 3;
    const int wm = w & 1, wn = w >> 1;
    const int mbase = m0 + wm * 32;
    const int nbase = wn * 32;
    float* Ws = smem;
    float* ssq = smem + 128 * WS_STRIDE;

    float acc[2][4][4];
#pragma unroll
    for (int i = 0; i < 2; i++)
#pragma unroll
        for (int j = 0; j < 4; j++)
#pragma unroll
            for (int q = 0; q < 4; q++) acc[i][j][q] = 0.f;

    bool vlo[2], vhi[2];
    int rlo[2], rhi[2];
#pragma unroll
    for (int i = 0; i < 2; i++) {
        rlo[i] = mbase + i * 16 + gid;
        rhi[i] = rlo[i] + 8;
        vlo[i] = rlo[i] < M;
        vhi[i] = rhi[i] < M;
    }

    for (int kt = 0; kt < KDIM; kt += 64) {
        __syncthreads();
#pragma unroll
        for (int it = 0; it < 8; it++) {
            int idx = tid + it * 256;
            int n = idx >> 4, q = idx & 15;
            float4 v = *(const float4*)(W + (size_t)n * KDIM + kt + q * 4);
            *(float4*)&Ws[n * WS_STRIDE + q * 4] = v;
        }
        __syncthreads();
#pragma unroll
        for (int k8 = 0; k8 < 8; k8++) {
            int kg = kt + k8 * 8;
            unsigned af[2][4];
#pragma unroll
            for (int i = 0; i < 2; i++) {
                const float* Alo = A + (size_t)rlo[i] * KDIM + kg + tig;
                const float* Ahi = A + (size_t)rhi[i] * KDIM + kg + tig;
                float a0 = vlo[i] ? Alo[0] : 0.f;
                float a1 = vhi[i] ? Ahi[0] : 0.f;
                float a2 = vlo[i] ? Alo[4] : 0.f;
                float a3 = vhi[i] ? Ahi[4] : 0.f;
                af[i][0] = f2tf32(a0); af[i][1] = f2tf32(a1);
                af[i][2] = f2tf32(a2); af[i][3] = f2tf32(a3);
            }
#pragma unroll
            for (int j = 0; j < 4; j++) {
                int n = nbase + j * 8 + gid;
                unsigned b0 = f2tf32(Ws[n * WS_STRIDE + k8 * 8 + tig]);
                unsigned b1 = f2tf32(Ws[n * WS_STRIDE + k8 * 8 + tig + 4]);
#pragma unroll
                for (int i = 0; i < 2; i++)
                    mma_tf32(acc[i][j], af[i][0], af[i][1], af[i][2], af[i][3], b0, b1);
            }
        }
    }

    if (bias) {
#pragma unroll
        for (int j = 0; j < 4; j++) {
            int col = nbase + j * 8 + 2 * tig;
            float bv0 = bias[col], bv1 = bias[col + 1];
#pragma unroll
            for (int i = 0; i < 2; i++) {
                acc[i][j][0] += bv0; acc[i][j][1] += bv1;
                acc[i][j][2] += bv0; acc[i][j][3] += bv1;
            }
        }
    }

    float mul_lo[2], mul_hi[2];
#pragma unroll
    for (int i = 0; i < 2; i++) { mul_lo[i] = 1.f; mul_hi[i] = 1.f; }

    if (NORM) {
        __syncthreads();
        if (tid < 64) ssq[tid] = 0.f;
        __syncthreads();
#pragma unroll
        for (int i = 0; i < 2; i++) {
            float plo = 0.f, phi = 0.f;
#pragma unroll
            for (int j = 0; j < 4; j++) {
                plo += acc[i][j][0] * acc[i][j][0] + acc[i][j][1] * acc[i][j][1];
                phi += acc[i][j][2] * acc[i][j][2] + acc[i][j][3] * acc[i][j][3];
            }
            plo += __shfl_xor_sync(0xffffffffu, plo, 1);
            plo += __shfl_xor_sync(0xffffffffu, plo, 2);
            phi += __shfl_xor_sync(0xffffffffu, phi, 1);
            phi += __shfl_xor_sync(0xffffffffu, phi, 2);
            if (tig == 0) {
                atomicAdd(&ssq[wm * 32 + i * 16 + gid], plo);
                atomicAdd(&ssq[wm * 32 + i * 16 + gid + 8], phi);
            }
        }
        __syncthreads();
#pragma unroll
        for (int i = 0; i < 2; i++) {
            mul_lo[i] = scale / fmaxf(sqrtf(ssq[wm * 32 + i * 16 + gid]), 1e-12f);
            mul_hi[i] = scale / fmaxf(sqrtf(ssq[wm * 32 + i * 16 + gid + 8]), 1e-12f);
        }
    }
    if (ROWSCALE) {
#pragma unroll
        for (int i = 0; i < 2; i++) {
            if (vlo[i]) mul_lo[i] *= rs[rlo[i]];
            if (vhi[i]) mul_hi[i] *= rs[rhi[i]];
        }
    }

#pragma unroll
    for (int i = 0; i < 2; i++) {
#pragma unroll
        for (int j = 0; j < 4; j++) {
            int col = nbase + j * 8 + 2 * tig;
            if (vlo[i]) {
                float2 o = make_float2(acc[i][j][0] * mul_lo[i], acc[i][j][1] * mul_lo[i]);
                *(float2*)(out + (size_t)rlo[i] * CH + col) = o;
            }
            if (vhi[i]) {
                float2 o = make_float2(acc[i][j][2] * mul_hi[i], acc[i][j][3] * mul_hi[i]);
                *(float2*)(out + (size_t)rhi[i] * CH + col) = o;
            }
        }
    }
}

// ---------------- z2 body: 8 rows/block, cp.async double-buffered smem staging ----------------
#define NVF4    2500          // float4 per x2 row
#define CHUNK_F4 128          // float4 per row per chunk (16KB per chunk across 8 rows)
#define NCHUNK  20            // ceil(2500/128)

__device__ __forceinline__ void cp_async16(unsigned int saddr, const void* gaddr) {
    asm volatile("cp.async.cg.shared.global [%0], [%1], 16;" :: "r"(saddr), "l"(gaddr));
}

__device__ __forceinline__ void z2_body8(const float* __restrict__ x2,
                                         const float* __restrict__ W22,
                                         int row0, float* smem) {
    const int tid = threadIdx.x, lane = tid & 31, wid = tid >> 5;
    float4* buf = (float4*)smem;                   // [2][8][128] float4 = 32KB
    float* red0 = smem + 8192;                     // [8][4]
    float* red1 = smem + 8224;                     // [8][4]
    const float4* __restrict__ w0 = (const float4*)W22;
    const float4* __restrict__ w1 = (const float4*)(W22 + N_NODES);

    // producer mapping: warp wid stages row wid; 32 lanes x 4 float4 = 128 float4/row
    const float4* __restrict__ myrow =
        (const float4*)(x2 + (size_t)(row0 + wid) * N_NODES);
    unsigned int sbase = (unsigned int)__cvta_generic_to_shared(buf);

#define Z2_ISSUE(c, bsel)                                                     \
    do {                                                                      \
        int _c = (c);                                                         \
        _Pragma("unroll")                                                     \
        for (int q = 0; q < 4; q++) {                                         \
            int j = _c * CHUNK_F4 + lane + q * 32;                            \
            if (j < NVF4)                                                     \
                cp_async16(sbase + (((bsel) * 1024 + wid * 128 + lane + q * 32) << 4), \
                           myrow + j);                                        \
        }                                                                     \
        asm volatile("cp.async.commit_group;");                               \
    } while (0)

    Z2_ISSUE(0, 0);
    Z2_ISSUE(1, 1);

    const int jl = tid & 127;       // consumer column within chunk
    const int half = tid >> 7;      // 0: rows 0-3, 1: rows 4-7
    float s0[4] = {0.f, 0.f, 0.f, 0.f}, s1[4] = {0.f, 0.f, 0.f, 0.f};

    // prefetch W22 values for chunk 0
    float4 wb0 = w0[jl], wb1 = w1[jl];

    for (int c = 0; c < NCHUNK; c++) {
        asm volatile("cp.async.wait_group 1;");
        __syncthreads();
        int j = c * CHUNK_F4 + jl;
        bool v = j < NVF4;
        float4 b = wb0, cc = wb1;
        int jn = j + CHUNK_F4;
        if (c + 1 < NCHUNK && jn < NVF4) { wb0 = w0[jn]; wb1 = w1[jn]; }
        if (v) {
            const float4* bp = buf + (c & 1) * 1024 + half * 512 + jl;
#pragma unroll
            for (int k = 0; k < 4; k++) {
                float4 a = bp[k * 128];
                s0[k] += a.x * b.x  + a.y * b.y  + a.z * b.z  + a.w * b.w;
                s1[k] += a.x * cc.x + a.y * cc.y + a.z * cc.z + a.w * cc.w;
            }
        }
        __syncthreads();
        if (c + 2 < NCHUNK) { Z2_ISSUE(c + 2, c & 1); }
        else { asm volatile("cp.async.commit_group;"); }
    }
#undef Z2_ISSUE

    // reduce: warp-level, then across 4 warps per half
#pragma unroll
    for (int k = 0; k < 4; k++) {
#pragma unroll
        for (int d = 16; d; d >>= 1) {
            s0[k] += __shfl_xor_sync(0xffffffffu, s0[k], d);
            s1[k] += __shfl_xor_sync(0xffffffffu, s1[k], d);
        }
    }
    if (lane == 0) {
        int wg = wid & 3;
#pragma unroll
        for (int k = 0; k < 4; k++) {
            red0[(half * 4 + k) * 4 + wg] = s0[k];
            red1[(half * 4 + k) * 4 + wg] = s1[k];
        }
    }
    __syncthreads();
    if (tid < 8) {
        float y0 = red0[tid * 4] + red0[tid * 4 + 1] + red0[tid * 4 + 2] + red0[tid * 4 + 3];
        float y1 = red1[tid * 4] + red1[tid * 4 + 1] + red1[tid * 4 + 2] + red1[tid * 4 + 3];
        float n = fmaxf(sqrtf(y0 * y0 + y1 * y1), 1e-12f);
        g_z2c0[row0 + tid] = 0.8f * y0 / n;
    }
}

// ---------------- fatA: gemm1 + cvt_count + z2 rows [0, 3800) ----------------
__global__ __launch_bounds__(256) void fatA_kernel(
    const float* __restrict__ x, const float* __restrict__ W2,
    const float* __restrict__ b2, const int* __restrict__ edge,
    const float* __restrict__ x2, const float* __restrict__ W22) {
    __shared__ float smem[SMEM_FLOATS];
    int b = blockIdx.x;
    if (b < GEMM_BLOCKS) {
        gemm_tf32_body<IN_DIM, true, false>(x, W2, b2, nullptr, g_h,
                                            N_NODES, 1.8f, b * 64, smem);
    } else if (b < GEMM_BLOCKS + AUX_BLOCKS) {
        cvt_count_body(edge, b - GEMM_BLOCKS);
    } else {
        z2_body8(x2, W22, (b - GEMM_BLOCKS - AUX_BLOCKS) * 8, smem);
    }
}

// ---------------- fatB: gemm2 + CSR fill + z2 rows [3800, 7200) ----------------
__global__ __launch_bounds__(256) void fatB_kernel(
    const float* __restrict__ Wg,
    const float* __restrict__ x2, const float* __restrict__ W22) {
    __shared__ float smem[SMEM_FLOATS];
    int b = blockIdx.x;
    if (b < GEMM_BLOCKS) {
        gemm_tf32_body<CH, false, true>(g_h, Wg, nullptr, g_dinv, g_xw,
                                        N_NODES, 1.0f, b * 64, smem);
    } else if (b < GEMM_BLOCKS + AUX_BLOCKS) {
        int bb = b - GEMM_BLOCKS;
        for (int e = threadIdx.x + bb * 256; e < N_EDGES; e += AUX_BLOCKS * 256) {
            int t = g_tgt[e];
            int p = atomicAdd(&g_pos[t], 1);
            int w = g_off[t] + p;
            g_adj[w] = g_src[e];
            g_eid[w] = e;
        }
    } else {
        z2_body8(x2, W22, 3800 + (b - GEMM_BLOCKS - AUX_BLOCKS) * 8, smem);
    }
}

// ---------------- gather body ----------------
__device__ __forceinline__ void gather_body(const float* __restrict__ bg,
                                            int i, int c) {
    float di = g_dinv[i];
    float acc = g_xw[i * CH + c];
    int s0 = g_off[i], s1 = g_off[i + 1];
    int j = s0;
    for (; j + 4 <= s1; j += 4) {
        int a0 = g_adj[j], a1 = g_adj[j + 1], a2 = g_adj[j + 2], a3 = g_adj[j + 3];
        float v0 = g_xw[a0 * CH + c], v1 = g_xw[a1 * CH + c];
        float v2 = g_xw[a2 * CH + c], v3 = g_xw[a3 * CH + c];
        acc += (v0 + v1) + (v2 + v3);
    }
    for (; j < s1; j++) acc += g_xw[g_adj[j] * CH + c];
    g_z1[i * CH + c] = acc * di + bg[c];
}

// ---------------- fatC: z2 rows [7200, 10000) + gather ----------------
#define GATHER_BLOCKS 5000
__global__ __launch_bounds__(256) void fatC_kernel(
    const float* __restrict__ bg,
    const float* __restrict__ x2, const float* __restrict__ W22) {
    __shared__ float smem[SMEM_FLOATS];
    int b = blockIdx.x;
    if (b < Z2C_BLK) {
        z2_body8(x2, W22, 7200 + b * 8, smem);
    } else {
        int g = b - Z2C_BLK;
        int node = g * 2 + (threadIdx.x >> 7);
        gather_body(bg, node, threadIdx.x & 127);
    }
}

// ---------------- decoder: warp per target node, CSR order, out[eid] ----------------
__global__ __launch_bounds__(256) void decoder_kernel(float* __restrict__ out) {
    int gtid = blockIdx.x * blockDim.x + threadIdx.x;
    if (gtid < N_NODES) { g_cnt[gtid] = 0; g_pos[gtid] = 0; }

    int node = gtid >> 5;
    int lane = threadIdx.x & 31;
    if (node >= N_NODES) return;
    float4 zc = *(const float4*)(g_z1 + (size_t)node * CH + lane * 4);
    float zc0 = g_z2c0[node];
    int s0 = g_off[node], s1 = g_off[node + 1];
    for (int j = s0; j < s1; j++) {
        int s = g_adj[j];
        const float4 a = *(const float4*)(g_z1 + (size_t)s * CH + lane * 4);
        float d = a.x * zc.x + a.y * zc.y + a.z * zc.z + a.w * zc.w;
#pragma unroll
        for (int o = 16; o; o >>= 1) d += __shfl_xor_sync(0xffffffffu, d, o);
        if (lane == 0) {
            float vn = g_z2c0[s] + zc0;
            float sf = 1.f / (1.f + __expf(-d));
            float sn = 1.f / (1.f + __expf(-vn));
            out[g_eid[j]] = sf * sf + (1.f - sf) * sn;
        }
    }
}

// ---------------- launch ----------------
extern "C" void kernel_launch(void* const* d_in, const int* in_sizes, int n_in,
                              void* d_out, int out_size) {
    const float* x    = (const float*)d_in[0];
    const float* x2   = (const float*)d_in[1];
    const float* W2   = (const float*)d_in[2];
    const float* b2   = (const float*)d_in[3];
    const float* Wg   = (const float*)d_in[4];
    const float* bg   = (const float*)d_in[5];
    const float* W22  = (const float*)d_in[6];
    const int*   edge = (const int*)d_in[7];
    float* out = (float*)d_out;

    fatA_kernel<<<GEMM_BLOCKS + AUX_BLOCKS + Z2A_BLK, 256>>>(x, W2, b2, edge, x2, W22);
    scan_kernel<<<1, 1024>>>();
    fatB_kernel<<<GEMM_BLOCKS + AUX_BLOCKS + Z2B_BLK, 256>>>(Wg, x2, W22);
    fatC_kernel<<<Z2C_BLK + GATHER_BLOCKS, 256>>>(bg, x2, W22);
    decoder_kernel<<<(N_NODES * 32 + 255) / 256, 256>>>(out);
}